// round 2
// baseline (speedup 1.0000x reference)
#include <cuda_runtime.h>
#include <math.h>

#define TT 32768          // 512 * 64 LSTM steps
#define D  128
#define G4 512            // 4*D gates

// ---------------- device scratch (static: no allocations allowed) ----------------
__device__ float d_LE[64*512*128];
__device__ float d_LD[64*512*128];
__device__ float d_Qe[64*512*128];
__device__ float d_Qd[64*512*128];
__device__ float d_SRCe[16*513*128];
__device__ float d_SRCd[16*513*128];
__device__ float d_Ke[16*513*128];
__device__ float d_Ve[16*513*128];
__device__ float d_Kd[16*513*128];
__device__ float d_Vd[16*513*128];
__device__ float d_S[64*512*513];      // scores buffer; later reused as G0 [TT*512]
__device__ float d_FeatE[64*512*128];
__device__ float d_FeatD[64*512*128];
__device__ float d_Flat[TT*128];       // enc in flat (t*64+b, d) layout
__device__ float d_X1[TT*128];         // layer0 -> layer1 h stream
__device__ float d_X2[TT*128];         // layer1 -> layer2 h stream
__device__ float d_LastH[64*128];
__device__ float g_Part[3*4*2*512];    // [layer][part][dblbuf][gate]
__device__ int   g_Flag[12];           // per (layer,part): published step count
__device__ int   g_XFlag[2];           // X1 / X2 published step count

// ---------------- memory-order helpers ----------------
__device__ __forceinline__ int ld_acq(const int* p) {
    int v;
    asm volatile("ld.acquire.gpu.s32 %0, [%1];" : "=r"(v) : "l"(p) : "memory");
    return v;
}
__device__ __forceinline__ void st_rel(int* p, int v) {
    asm volatile("st.release.gpu.s32 [%0], %1;" :: "l"(p), "r"(v) : "memory");
}

// ---------------- generic tiled GEMM: C = alpha * A(MxK) * B^T(or B) + bias ----------------
// A indexed [m*lda + k], B indexed transB? [n*ldb+k] : [k*ldb+n], C [m*ldc+n]
// batch z: A += (z/divA)*sA ; B += (z/divB)*sB ; C += z*sC
__global__ void gemm_k(const float* __restrict__ A, const float* __restrict__ B,
                       float* __restrict__ C, const float* __restrict__ bias,
                       int M, int N, int K, int lda, int ldb, int ldc,
                       long long sA, int divA, long long sB, int divB, long long sC,
                       float alpha, int transB, int accum)
{
    int bz = blockIdx.z;
    const float* Ab = A + (long long)(bz / divA) * sA;
    const float* Bb = B + (long long)(bz / divB) * sB;
    float*       Cb = C + (long long)bz * sC;

    int m0 = blockIdx.y * 64, n0 = blockIdx.x * 64;
    int tx = threadIdx.x, ty = threadIdx.y;
    int tid = ty * 16 + tx;

    __shared__ float As[16][64];
    __shared__ float Bs[16][64];

    float acc[4][4];
#pragma unroll
    for (int i = 0; i < 4; i++)
#pragma unroll
        for (int j = 0; j < 4; j++) acc[i][j] = 0.f;

    for (int k0 = 0; k0 < K; k0 += 16) {
#pragma unroll
        for (int e = 0; e < 4; e++) {
            int idx = tid + 256 * e;
            int kk = idx & 15, m = idx >> 4;
            int gm = m0 + m, gk = k0 + kk;
            As[kk][m] = (gm < M && gk < K) ? Ab[(long long)gm * lda + gk] : 0.f;
        }
        if (transB) {
#pragma unroll
            for (int e = 0; e < 4; e++) {
                int idx = tid + 256 * e;
                int kk = idx & 15, n = idx >> 4;
                int gn = n0 + n, gk = k0 + kk;
                Bs[kk][n] = (gn < N && gk < K) ? Bb[(long long)gn * ldb + gk] : 0.f;
            }
        } else {
#pragma unroll
            for (int e = 0; e < 4; e++) {
                int idx = tid + 256 * e;
                int n = idx & 63, kk = idx >> 6;
                int gn = n0 + n, gk = k0 + kk;
                Bs[kk][n] = (gn < N && gk < K) ? Bb[(long long)gk * ldb + gn] : 0.f;
            }
        }
        __syncthreads();
#pragma unroll
        for (int kk = 0; kk < 16; kk++) {
            float4 a4 = *(const float4*)&As[kk][ty * 4];
            float4 b4 = *(const float4*)&Bs[kk][tx * 4];
            acc[0][0] += a4.x * b4.x; acc[0][1] += a4.x * b4.y; acc[0][2] += a4.x * b4.z; acc[0][3] += a4.x * b4.w;
            acc[1][0] += a4.y * b4.x; acc[1][1] += a4.y * b4.y; acc[1][2] += a4.y * b4.z; acc[1][3] += a4.y * b4.w;
            acc[2][0] += a4.z * b4.x; acc[2][1] += a4.z * b4.y; acc[2][2] += a4.z * b4.z; acc[2][3] += a4.z * b4.w;
            acc[3][0] += a4.w * b4.x; acc[3][1] += a4.w * b4.y; acc[3][2] += a4.w * b4.z; acc[3][3] += a4.w * b4.w;
        }
        __syncthreads();
    }

#pragma unroll
    for (int i = 0; i < 4; i++) {
        int gm = m0 + ty * 4 + i;
        if (gm >= M) continue;
#pragma unroll
        for (int j = 0; j < 4; j++) {
            int gn = n0 + tx * 4 + j;
            if (gn >= N) continue;
            float v = alpha * acc[i][j] + (bias ? bias[gn] : 0.f);
            long long off = (long long)gm * ldc + gn;
            Cb[off] = accum ? (Cb[off] + v) : v;
        }
    }
}

// ---------------- softmax over last dim (n=513), one block per row ----------------
__global__ void softmax_rows(float* __restrict__ S, int n)
{
    float* row = S + (long long)blockIdx.x * n;
    int tid = threadIdx.x;
    __shared__ float red[128];

    float m = -1e30f;
    for (int i = tid; i < n; i += 128) m = fmaxf(m, row[i]);
    red[tid] = m; __syncthreads();
    for (int off = 64; off; off >>= 1) { if (tid < off) red[tid] = fmaxf(red[tid], red[tid + off]); __syncthreads(); }
    float mx = red[0]; __syncthreads();

    float s = 0.f;
    for (int i = tid; i < n; i += 128) { float e = expf(row[i] - mx); row[i] = e; s += e; }
    red[tid] = s; __syncthreads();
    for (int off = 64; off; off >>= 1) { if (tid < off) red[tid] += red[tid + off]; __syncthreads(); }
    float inv = 1.f / red[0];
    __syncthreads();
    for (int i = tid; i < n; i += 128) row[i] *= inv;
}

// ---------------- misc small kernels ----------------
__global__ void fill_pf(const float* __restrict__ pf)
{
    int sb = blockIdx.x, d = threadIdx.x;
    float v = 1e-5f * pf[sb * 128 + d];
    d_SRCe[(long long)sb * 513 * 128 + d] = v;
    d_SRCd[(long long)sb * 513 * 128 + d] = v;
}

__global__ void reset_flags()
{
    int t = threadIdx.x;
    if (t < 12) g_Flag[t] = 0;
    if (t < 2)  g_XFlag[t] = 0;
}

// ---------------- the sequential LSTM: 12 persistent CTAs ----------------
// layer l = blockIdx.x>>2, k-part c = blockIdx.x&3.
// Each CTA holds W_hh[l][:, 32c:32c+32] (+ W_ih for l>0) in registers (thread j <-> gate row j),
// computes a partial gate vector, all-exchanges partials through L2 (release/acquire flags),
// then every CTA redundantly computes (h,c). Layer handoffs stream through d_X1/d_X2.
__device__ __forceinline__ float sigf(float x) { return 1.f / (1.f + expf(-x)); }

__global__ void __launch_bounds__(512, 1) lstm_kernel(
    const float* __restrict__ G0,     // [TT][512] = flat@W_ih0^T + b_ih0
    const float* __restrict__ W_ih,   // [3][512][128]
    const float* __restrict__ W_hh,   // [3][512][128]
    const float* __restrict__ b_ih,   // [3][512]
    const float* __restrict__ b_hh)   // [3][512]
{
    const int l = blockIdx.x >> 2;
    const int c = blockIdx.x & 3;
    const int j = threadIdx.x;

    float whh[32], wih[32];
#pragma unroll
    for (int kk = 0; kk < 32; kk++)
        whh[kk] = W_hh[((l * 512 + j) << 7) + (c << 5) + kk];
    if (l > 0) {
#pragma unroll
        for (int kk = 0; kk < 32; kk++)
            wih[kk] = W_ih[((l * 512 + j) << 7) + (c << 5) + kk];
    } else {
#pragma unroll
        for (int kk = 0; kk < 32; kk++) wih[kk] = 0.f;
    }

    float bias = 0.f;
    if (c == 0) bias = (l == 0) ? b_hh[j] : (b_ih[l * 512 + j] + b_hh[l * 512 + j]);

    __shared__ float sh_h[128], sh_c[128], sh_x[128], sh_g[512];
    if (j < 128) { sh_h[j] = 0.f; sh_c[j] = 0.f; }
    __syncthreads();

    const float* Xin  = (l == 1) ? d_X1 : d_X2;   // unused for l==0
    float*       Xout = (l == 0) ? d_X1 : d_X2;   // unused for l==2
    int* myflag = &g_Flag[l * 4 + c];

    const bool isG0 = (l == 0 && c == 0);
    float g0cur = isG0 ? G0[j] : 0.f;

    for (int t = 0; t < TT; t++) {
        if (l > 0) {
            if (j == 0) { while (ld_acq(&g_XFlag[l - 1]) < t + 1) {} }
            __syncthreads();
            if (j < 32) ((float4*)sh_x)[j] = ((const float4*)Xin)[t * 32 + j];
            __syncthreads();
        }

        // partial gate matvec over this CTA's k-slice
        float p = bias;
        if (isG0) p += g0cur;
        {
            const float4* h4 = (const float4*)&sh_h[c * 32];
#pragma unroll
            for (int q = 0; q < 8; q++) {
                float4 hv = h4[q];
                p += whh[q * 4 + 0] * hv.x + whh[q * 4 + 1] * hv.y
                   + whh[q * 4 + 2] * hv.z + whh[q * 4 + 3] * hv.w;
            }
            if (l > 0) {
                const float4* x4 = (const float4*)&sh_x[c * 32];
#pragma unroll
                for (int q = 0; q < 8; q++) {
                    float4 xv = x4[q];
                    p += wih[q * 4 + 0] * xv.x + wih[q * 4 + 1] * xv.y
                       + wih[q * 4 + 2] * xv.z + wih[q * 4 + 3] * xv.w;
                }
            }
        }
        // prefetch next step's G0 (off the critical path: overlaps the exchange)
        if (isG0 && t + 1 < TT) g0cur = __ldg(&G0[(t + 1) * 512 + j]);

        // publish partial
        g_Part[((l * 4 + c) * 2 + (t & 1)) * 512 + j] = p;
        __syncthreads();
        if (j == 0) st_rel(myflag, t + 1);

        // wait all 4 parts, gather
        if (j < 4) { while (ld_acq(&g_Flag[l * 4 + j]) < t + 1) {} }
        __syncthreads();
        float g = 0.f;
#pragma unroll
        for (int c2 = 0; c2 < 4; c2++)
            g += g_Part[((l * 4 + c2) * 2 + (t & 1)) * 512 + j];
        sh_g[j] = g;
        __syncthreads();

        // elementwise LSTM cell (i,f,g,o row blocks)
        if (j < 128) {
            float gi = sh_g[j], gf = sh_g[128 + j], gc = sh_g[256 + j], go = sh_g[384 + j];
            float cc = sigf(gf) * sh_c[j] + sigf(gi) * tanhf(gc);
            float hh = sigf(go) * tanhf(cc);
            sh_c[j] = cc;
            sh_h[j] = hh;
            if (c == 0) {
                if (l < 2) Xout[t * 128 + j] = hh;
                else if (t >= TT - 64) d_LastH[(t - (TT - 64)) * 128 + j] = hh;
            }
        }
        __syncthreads();
        if (l < 2 && c == 0 && j == 0) st_rel(&g_XFlag[l], t + 1);
    }
}

// ---------------- final FC head: 64 blocks x 128 threads ----------------
__global__ void fc_kernel(const float* __restrict__ W1, const float* __restrict__ b1,
                          const float* __restrict__ W2, const float* __restrict__ b2,
                          float* __restrict__ out)
{
    int b = blockIdx.x, tid = threadIdx.x;
    __shared__ float sh[128];
    __shared__ float red[128];
    sh[tid] = d_LastH[b * 128 + tid];
    __syncthreads();
    float s = b1[tid];
    const float* w = W1 + tid * 128;
#pragma unroll 4
    for (int k = 0; k < 128; k++) s += w[k] * sh[k];
    s = fmaxf(s, 0.f) * W2[tid];
    red[tid] = s; __syncthreads();
    for (int off = 64; off; off >>= 1) { if (tid < off) red[tid] += red[tid + off]; __syncthreads(); }
    if (tid == 0) out[b] = 1.f / (1.f + expf(-(red[0] + b2[0])));
}

// ---------------- host ----------------
static void launch_gemm(const float* A, const float* B, float* C, const float* bias,
                        int M, int N, int K, int lda, int ldb, int ldc,
                        long long sA, int divA, long long sB, int divB, long long sC,
                        int batch, float alpha, int transB, int accum)
{
    dim3 grid((N + 63) / 64, (M + 63) / 64, batch), blk(16, 16);
    gemm_k<<<grid, blk>>>(A, B, C, bias, M, N, K, lda, ldb, ldc,
                          sA, divA, sB, divB, sC, alpha, transB, accum);
}

template <typename T>
static float* sym_addr(const T& s)
{
    void* p = nullptr;
    cudaGetSymbolAddress(&p, s);
    return (float*)p;
}

extern "C" void kernel_launch(void* const* d_in, const int* in_sizes, int n_in,
                              void* d_out, int out_size)
{
    const float* sp_emo = (const float*)d_in[0];   // (16,512,25)
    const float* li_emo = (const float*)d_in[1];   // (64,512,25)
    const float* sp_3d  = (const float*)d_in[2];   // (16,512,58)
    const float* li_3d  = (const float*)d_in[3];   // (64,512,58)
    const float* pf     = (const float*)d_in[4];   // (16,128)

    // 'repeat_interleave' is a size-1 scalar inserted at dict index 5 in
    // setup_inputs(); weights start after it. Auto-detect for robustness.
    int off = (in_sizes[5] == 1) ? 1 : 0;
    const float* W_em = (const float*)d_in[5 + off],  *b_em = (const float*)d_in[6 + off];
    const float* W_3d = (const float*)d_in[7 + off],  *b_3d = (const float*)d_in[8 + off];
    const float* Wq_e = (const float*)d_in[9 + off],  *bq_e = (const float*)d_in[10 + off];
    const float* Wk_e = (const float*)d_in[11 + off], *bk_e = (const float*)d_in[12 + off];
    const float* Wv_e = (const float*)d_in[13 + off], *bv_e = (const float*)d_in[14 + off];
    const float* Wq_d = (const float*)d_in[15 + off], *bq_d = (const float*)d_in[16 + off];
    const float* Wk_d = (const float*)d_in[17 + off], *bk_d = (const float*)d_in[18 + off];
    const float* Wv_d = (const float*)d_in[19 + off], *bv_d = (const float*)d_in[20 + off];
    const float* W_fus = (const float*)d_in[21 + off], *b_fus = (const float*)d_in[22 + off];
    const float* W_fc1 = (const float*)d_in[23 + off], *b_fc1 = (const float*)d_in[24 + off];
    const float* W_fc2 = (const float*)d_in[25 + off], *b_fc2 = (const float*)d_in[26 + off];
    const float* W_ih = (const float*)d_in[27 + off];    // (3,512,128)
    const float* W_hh = (const float*)d_in[28 + off];    // (3,512,128)
    const float* b_ih = (const float*)d_in[29 + off];    // (3,512)
    const float* b_hh = (const float*)d_in[30 + off];    // (3,512)

    float* pLE    = sym_addr(d_LE);
    float* pLD    = sym_addr(d_LD);
    float* pQe    = sym_addr(d_Qe);
    float* pQd    = sym_addr(d_Qd);
    float* pSRCe  = sym_addr(d_SRCe);
    float* pSRCd  = sym_addr(d_SRCd);
    float* pKe    = sym_addr(d_Ke);
    float* pVe    = sym_addr(d_Ve);
    float* pKd    = sym_addr(d_Kd);
    float* pVd    = sym_addr(d_Vd);
    float* pS     = sym_addr(d_S);
    float* pFeatE = sym_addr(d_FeatE);
    float* pFeatD = sym_addr(d_FeatD);
    float* pFlat  = sym_addr(d_Flat);

    const float inv_sqrt_d = 1.0f / sqrtf(128.0f);

    reset_flags<<<1, 32>>>();
    fill_pf<<<16, 128>>>(pf);

    // --- encoders ---
    // LE = li_emo @ W_em^T + b_em            (64,512,128)
    launch_gemm(li_emo, W_em, pLE, b_em, 512, 128, 25, 25, 25, 128,
                512LL * 25, 1, 0, 1, 512LL * 128, 64, 1.f, 1, 0);
    // SE16 -> SRCe rows 1..512
    launch_gemm(sp_emo, W_em, pSRCe + 128, b_em, 512, 128, 25, 25, 25, 128,
                512LL * 25, 1, 0, 1, 513LL * 128, 16, 1.f, 1, 0);
    // LD = li_3d @ W_3d^T + b_3d
    launch_gemm(li_3d, W_3d, pLD, b_3d, 512, 128, 58, 58, 58, 128,
                512LL * 58, 1, 0, 1, 512LL * 128, 64, 1.f, 1, 0);
    // SD16 -> SRCd rows 1..512
    launch_gemm(sp_3d, W_3d, pSRCd + 128, b_3d, 512, 128, 58, 58, 58, 128,
                512LL * 58, 1, 0, 1, 513LL * 128, 16, 1.f, 1, 0);

    // --- QKV ---
    launch_gemm(pSRCe, Wk_e, pKe, bk_e, 513, 128, 128, 128, 128, 128,
                513LL * 128, 1, 0, 1, 513LL * 128, 16, 1.f, 1, 0);
    launch_gemm(pSRCe, Wv_e, pVe, bv_e, 513, 128, 128, 128, 128, 128,
                513LL * 128, 1, 0, 1, 513LL * 128, 16, 1.f, 1, 0);
    launch_gemm(pLE, Wq_e, pQe, bq_e, 512, 128, 128, 128, 128, 128,
                512LL * 128, 1, 0, 1, 512LL * 128, 64, 1.f, 1, 0);
    launch_gemm(pSRCd, Wk_d, pKd, bk_d, 513, 128, 128, 128, 128, 128,
                513LL * 128, 1, 0, 1, 513LL * 128, 16, 1.f, 1, 0);
    launch_gemm(pSRCd, Wv_d, pVd, bv_d, 513, 128, 128, 128, 128, 128,
                513LL * 128, 1, 0, 1, 513LL * 128, 16, 1.f, 1, 0);
    launch_gemm(pLD, Wq_d, pQd, bq_d, 512, 128, 128, 128, 128, 128,
                512LL * 128, 1, 0, 1, 512LL * 128, 64, 1.f, 1, 0);

    // --- attention (emo) ---
    launch_gemm(pQe, pKe, pS, nullptr, 512, 513, 128, 128, 128, 513,
                512LL * 128, 1, 513LL * 128, 4, 512LL * 513, 64, inv_sqrt_d, 1, 0);
    softmax_rows<<<64 * 512, 128>>>(pS, 513);
    launch_gemm(pS, pVe, pFeatE, nullptr, 512, 128, 513, 513, 128, 128,
                512LL * 513, 1, 513LL * 128, 4, 512LL * 128, 64, 1.f, 0, 0);

    // --- attention (3dmm) ---
    launch_gemm(pQd, pKd, pS, nullptr, 512, 513, 128, 128, 128, 513,
                512LL * 128, 1, 513LL * 128, 4, 512LL * 513, 64, inv_sqrt_d, 1, 0);
    softmax_rows<<<64 * 512, 128>>>(pS, 513);
    launch_gemm(pS, pVd, pFeatD, nullptr, 512, 128, 513, 513, 128, 128,
                512LL * 513, 1, 513LL * 128, 4, 512LL * 128, 64, 1.f, 0, 0);

    // --- fusion, written directly into flat (t*64+b, d) layout ---
    launch_gemm(pFeatE, W_fus, pFlat, b_fus, 512, 128, 128, 128, 256, 64 * 128,
                512LL * 128, 1, 0, 1, 128LL, 64, 1.f, 1, 0);
    launch_gemm(pFeatD, W_fus + 128, pFlat, nullptr, 512, 128, 128, 128, 256, 64 * 128,
                512LL * 128, 1, 0, 1, 128LL, 64, 1.f, 1, 1);

    // --- G0 = flat @ W_ih[0]^T + b_ih[0]   (reuses d_S storage) ---
    launch_gemm(pFlat, W_ih, pS, b_ih, TT, 512, 128, 128, 128, 512,
                0, 1, 0, 1, 0, 1, 1.f, 1, 0);

    // --- sequential 3-layer LSTM over 32768 steps ---
    lstm_kernel<<<12, 512>>>(pS, W_ih, W_hh, b_ih, b_hh);

    // --- head ---
    fc_kernel<<<64, 128>>>(W_fc1, b_fc1, W_fc2, b_fc2, (float*)d_out);
}

// round 3
// speedup vs baseline: 1.0744x; 1.0744x over previous
#include <cuda_runtime.h>
#include <math.h>
#include <stdint.h>

#define TT 32768          // 512 * 64 LSTM steps
#define D  128

// ---------------- device scratch (static: no allocations allowed) ----------------
__device__ float d_LE[64*512*128];
__device__ float d_LD[64*512*128];
__device__ float d_Qe[64*512*128];
__device__ float d_Qd[64*512*128];
__device__ float d_SRCe[16*513*128];
__device__ float d_SRCd[16*513*128];
__device__ float d_Ke[16*513*128];
__device__ float d_Ve[16*513*128];
__device__ float d_Kd[16*513*128];
__device__ float d_Vd[16*513*128];
__device__ float d_S[64*512*513];      // scores buffer; later reused as G0 [TT*512]
__device__ float d_FeatE[64*512*128];
__device__ float d_FeatD[64*512*128];
__device__ float d_Flat[TT*128];       // enc in flat (t*64+b, d) layout
__device__ float d_X1[TT*128];         // layer0 -> layer1 h stream
__device__ float d_X2[TT*128];         // layer1 -> layer2 h stream
__device__ float d_LastH[64*128];
__device__ int   g_XFlag[2];           // X1 / X2 published step count

// ---------------- memory-order helpers ----------------
__device__ __forceinline__ int ld_acq(const int* p) {
    int v;
    asm volatile("ld.acquire.gpu.s32 %0, [%1];" : "=r"(v) : "l"(p) : "memory");
    return v;
}
__device__ __forceinline__ void st_rel(int* p, int v) {
    asm volatile("st.release.gpu.s32 [%0], %1;" :: "l"(p), "r"(v) : "memory");
}
__device__ __forceinline__ void stg_rel_f32(float* p, float v) {
    asm volatile("st.release.gpu.f32 [%0], %1;" :: "l"(p), "f"(v) : "memory");
}

// ---------------- cluster / mbarrier / f32x2 helpers ----------------
__device__ __forceinline__ uint32_t smem_u32(const void* p) {
    uint32_t a;
    asm("{ .reg .u64 t; cvta.to.shared.u64 t, %1; cvt.u32.u64 %0, t; }" : "=r"(a) : "l"(p));
    return a;
}
__device__ __forceinline__ uint32_t ctarank() {
    uint32_t r; asm("mov.u32 %0, %%cluster_ctarank;" : "=r"(r)); return r;
}
__device__ __forceinline__ uint32_t mapa_r(uint32_t addr, uint32_t rank) {
    uint32_t r; asm("mapa.shared::cluster.u32 %0, %1, %2;" : "=r"(r) : "r"(addr), "r"(rank));
    return r;
}
__device__ __forceinline__ void st_cluster_f32(uint32_t raddr, float v) {
    asm volatile("st.shared::cluster.f32 [%0], %1;" :: "r"(raddr), "f"(v) : "memory");
}
__device__ __forceinline__ void mbar_init(uint32_t addr, uint32_t cnt) {
    asm volatile("mbarrier.init.shared.b64 [%0], %1;" :: "r"(addr), "r"(cnt) : "memory");
}
__device__ __forceinline__ void mbar_arrive_cluster(uint32_t raddr) {
    asm volatile("mbarrier.arrive.release.cluster.shared::cluster.b64 _, [%0];"
                 :: "r"(raddr) : "memory");
}
__device__ __forceinline__ void mbar_wait_parity(uint32_t addr, uint32_t parity) {
    asm volatile(
        "{\n\t"
        ".reg .pred P;\n\t"
        "LAB_%=:\n\t"
        "mbarrier.try_wait.parity.acquire.cluster.shared::cta.b64 P, [%0], %1, 0x989680;\n\t"
        "@P bra DONE_%=;\n\t"
        "bra LAB_%=;\n\t"
        "DONE_%=:\n\t"
        "}" :: "r"(addr), "r"(parity) : "memory");
}
__device__ __forceinline__ void cluster_sync_() {
    asm volatile("barrier.cluster.arrive.aligned;" ::: "memory");
    asm volatile("barrier.cluster.wait.aligned;" ::: "memory");
}
__device__ __forceinline__ unsigned long long pk2(float a, float b) {
    unsigned long long r;
    asm("mov.b64 %0, {%1, %2};" : "=l"(r) : "f"(a), "f"(b));
    return r;
}
__device__ __forceinline__ void fma2(unsigned long long& acc, unsigned long long a, unsigned long long b) {
    asm("fma.rn.f32x2 %0, %1, %2, %0;" : "+l"(acc) : "l"(a), "l"(b));
}
__device__ __forceinline__ float upk_sum(unsigned long long v) {
    float lo, hi;
    asm("mov.b64 {%0, %1}, %2;" : "=f"(lo), "=f"(hi) : "l"(v));
    return lo + hi;
}

// ---------------- generic tiled GEMM (parallel phase; unchanged) ----------------
__global__ void gemm_k(const float* __restrict__ A, const float* __restrict__ B,
                       float* __restrict__ C, const float* __restrict__ bias,
                       int M, int N, int K, int lda, int ldb, int ldc,
                       long long sA, int divA, long long sB, int divB, long long sC,
                       float alpha, int transB, int accum)
{
    int bz = blockIdx.z;
    const float* Ab = A + (long long)(bz / divA) * sA;
    const float* Bb = B + (long long)(bz / divB) * sB;
    float*       Cb = C + (long long)bz * sC;

    int m0 = blockIdx.y * 64, n0 = blockIdx.x * 64;
    int tx = threadIdx.x, ty = threadIdx.y;
    int tid = ty * 16 + tx;

    __shared__ float As[16][64];
    __shared__ float Bs[16][64];

    float acc[4][4];
#pragma unroll
    for (int i = 0; i < 4; i++)
#pragma unroll
        for (int j = 0; j < 4; j++) acc[i][j] = 0.f;

    for (int k0 = 0; k0 < K; k0 += 16) {
#pragma unroll
        for (int e = 0; e < 4; e++) {
            int idx = tid + 256 * e;
            int kk = idx & 15, m = idx >> 4;
            int gm = m0 + m, gk = k0 + kk;
            As[kk][m] = (gm < M && gk < K) ? Ab[(long long)gm * lda + gk] : 0.f;
        }
        if (transB) {
#pragma unroll
            for (int e = 0; e < 4; e++) {
                int idx = tid + 256 * e;
                int kk = idx & 15, n = idx >> 4;
                int gn = n0 + n, gk = k0 + kk;
                Bs[kk][n] = (gn < N && gk < K) ? Bb[(long long)gn * ldb + gk] : 0.f;
            }
        } else {
#pragma unroll
            for (int e = 0; e < 4; e++) {
                int idx = tid + 256 * e;
                int n = idx & 63, kk = idx >> 6;
                int gn = n0 + n, gk = k0 + kk;
                Bs[kk][n] = (gn < N && gk < K) ? Bb[(long long)gk * ldb + gn] : 0.f;
            }
        }
        __syncthreads();
#pragma unroll
        for (int kk = 0; kk < 16; kk++) {
            float4 a4 = *(const float4*)&As[kk][ty * 4];
            float4 b4 = *(const float4*)&Bs[kk][tx * 4];
            acc[0][0] += a4.x * b4.x; acc[0][1] += a4.x * b4.y; acc[0][2] += a4.x * b4.z; acc[0][3] += a4.x * b4.w;
            acc[1][0] += a4.y * b4.x; acc[1][1] += a4.y * b4.y; acc[1][2] += a4.y * b4.z; acc[1][3] += a4.y * b4.w;
            acc[2][0] += a4.z * b4.x; acc[2][1] += a4.z * b4.y; acc[2][2] += a4.z * b4.z; acc[2][3] += a4.z * b4.w;
            acc[3][0] += a4.w * b4.x; acc[3][1] += a4.w * b4.y; acc[3][2] += a4.w * b4.z; acc[3][3] += a4.w * b4.w;
        }
        __syncthreads();
    }

#pragma unroll
    for (int i = 0; i < 4; i++) {
        int gm = m0 + ty * 4 + i;
        if (gm >= M) continue;
#pragma unroll
        for (int j = 0; j < 4; j++) {
            int gn = n0 + tx * 4 + j;
            if (gn >= N) continue;
            float v = alpha * acc[i][j] + (bias ? bias[gn] : 0.f);
            long long off = (long long)gm * ldc + gn;
            Cb[off] = accum ? (Cb[off] + v) : v;
        }
    }
}

// ---------------- softmax over last dim (n=513), one block per row ----------------
__global__ void softmax_rows(float* __restrict__ S, int n)
{
    float* row = S + (long long)blockIdx.x * n;
    int tid = threadIdx.x;
    __shared__ float red[128];

    float m = -1e30f;
    for (int i = tid; i < n; i += 128) m = fmaxf(m, row[i]);
    red[tid] = m; __syncthreads();
    for (int off = 64; off; off >>= 1) { if (tid < off) red[tid] = fmaxf(red[tid], red[tid + off]); __syncthreads(); }
    float mx = red[0]; __syncthreads();

    float s = 0.f;
    for (int i = tid; i < n; i += 128) { float e = expf(row[i] - mx); row[i] = e; s += e; }
    red[tid] = s; __syncthreads();
    for (int off = 64; off; off >>= 1) { if (tid < off) red[tid] += red[tid + off]; __syncthreads(); }
    float inv = 1.f / red[0];
    __syncthreads();
    for (int i = tid; i < n; i += 128) row[i] *= inv;
}

// ---------------- misc small kernels ----------------
__global__ void fill_pf(const float* __restrict__ pf)
{
    int sb = blockIdx.x, d = threadIdx.x;
    float v = 1e-5f * pf[sb * 128 + d];
    d_SRCe[(long long)sb * 513 * 128 + d] = v;
    d_SRCd[(long long)sb * 513 * 128 + d] = v;
}

__global__ void reset_flags()
{
    int t = threadIdx.x;
    if (t < 2) g_XFlag[t] = 0;
}

// ---------------- sequential 3-layer LSTM: 3 clusters x 4 CTAs, DSMEM exchange ----
// Cluster = one layer. CTA rank c owns global h-indices J in [32c, 32c+32).
// Thread (j, s): j = tid>>4 local h-idx, s = tid&15 k-slice of 8.
// Each thread computes 4 gate rows (i,f,g,o for its J) over its k-slice with
// packed f32x2 FMAs; 16-lane shfl reduce puts all 4 full gates into lane s==0,
// which runs the cell in-registers (c-state never leaves RF) and pushes its h
// to all 4 CTAs' sh_h via st.shared::cluster + mbarrier arrive (release.cluster).
__device__ __forceinline__ float sigf(float x) { return 1.f / (1.f + expf(-x)); }

__global__ void __launch_bounds__(512, 1) __cluster_dims__(4, 1, 1) lstm_kernel(
    const float* __restrict__ G0,     // [TT][512] = flat@W_ih0^T + b_ih0
    const float* __restrict__ W_ih,   // [3][512][128]
    const float* __restrict__ W_hh,   // [3][512][128]
    const float* __restrict__ b_ih,   // [3][512]
    const float* __restrict__ b_hh)   // [3][512]
{
    const int l   = blockIdx.x >> 2;
    const uint32_t c = ctarank();
    const int tid = threadIdx.x;
    const int j   = tid >> 4;
    const int s   = tid & 15;
    const int J   = (int)c * 32 + j;
    const bool isCell = (s == 0);

    // ---- register-resident weights: 4 gates x 4 packed pairs, k in [8s, 8s+8) ----
    unsigned long long whh[4][4], wih[4][4];
#pragma unroll
    for (int G = 0; G < 4; G++) {
        int R = l * 512 + G * 128 + J;
#pragma unroll
        for (int q = 0; q < 4; q++) {
            float2 w = *(const float2*)&W_hh[(long long)R * 128 + 8 * s + 2 * q];
            whh[G][q] = pk2(w.x, w.y);
        }
    }
    if (l > 0) {
#pragma unroll
        for (int G = 0; G < 4; G++) {
            int R = l * 512 + G * 128 + J;
#pragma unroll
            for (int q = 0; q < 4; q++) {
                float2 w = *(const float2*)&W_ih[(long long)R * 128 + 8 * s + 2 * q];
                wih[G][q] = pk2(w.x, w.y);
            }
        }
    } else {
#pragma unroll
        for (int G = 0; G < 4; G++)
#pragma unroll
            for (int q = 0; q < 4; q++) wih[G][q] = 0ull;
    }

    float bias[4];
#pragma unroll
    for (int G = 0; G < 4; G++) {
        int R = l * 512 + G * 128 + J;
        bias[G] = b_hh[R] + (l > 0 ? b_ih[R] : 0.f);
    }

    __shared__ float sh_h[2][128];
    __shared__ float sh_x[128];
    __shared__ __align__(8) unsigned long long mbar;

    if (tid < 128) { sh_h[0][tid] = 0.f; sh_h[1][tid] = 0.f; }
    const uint32_t mbar_a = smem_u32(&mbar);
    if (tid == 0) mbar_init(mbar_a, 128);
    __syncthreads();
    cluster_sync_();

    const float* Xin  = (l == 1) ? d_X1 : d_X2;
    float*       Xout = (l == 0) ? d_X1 : d_X2;

    float g0next[4] = {0.f, 0.f, 0.f, 0.f};
    if (l == 0 && isCell) {
#pragma unroll
        for (int G = 0; G < 4; G++) g0next[G] = __ldg(&G0[G * 128 + J]);
    }
    float cst = 0.f;

    const uint32_t h_base = smem_u32(&sh_h[0][0]);

    for (int t = 0; t < TT; t++) {
        if (l > 0) {
            if (tid == 0) { while (ld_acq(&g_XFlag[l - 1]) < t + 1) {} }
            __syncthreads();
            if (tid < 32) ((float4*)sh_x)[tid] = ((const float4*)(Xin + t * 128))[tid];
            __syncthreads();
        }

        const int rb = (t & 1) ^ 1;   // read buffer (h from step t-1)

        // ---- packed matvec over this thread's k-slice ----
        unsigned long long acc[4] = {0ull, 0ull, 0ull, 0ull};
        {
            float4 h0 = *(const float4*)&sh_h[rb][8 * s];
            float4 h1 = *(const float4*)&sh_h[rb][8 * s + 4];
            unsigned long long hp[4] = { pk2(h0.x, h0.y), pk2(h0.z, h0.w),
                                         pk2(h1.x, h1.y), pk2(h1.z, h1.w) };
#pragma unroll
            for (int G = 0; G < 4; G++) {
                fma2(acc[G], whh[G][0], hp[0]);
                fma2(acc[G], whh[G][1], hp[1]);
                fma2(acc[G], whh[G][2], hp[2]);
                fma2(acc[G], whh[G][3], hp[3]);
            }
            if (l > 0) {
                float4 x0 = *(const float4*)&sh_x[8 * s];
                float4 x1 = *(const float4*)&sh_x[8 * s + 4];
                unsigned long long xp[4] = { pk2(x0.x, x0.y), pk2(x0.z, x0.w),
                                             pk2(x1.x, x1.y), pk2(x1.z, x1.w) };
#pragma unroll
                for (int G = 0; G < 4; G++) {
                    fma2(acc[G], wih[G][0], xp[0]);
                    fma2(acc[G], wih[G][1], xp[1]);
                    fma2(acc[G], wih[G][2], xp[2]);
                    fma2(acc[G], wih[G][3], xp[3]);
                }
            }
        }
        float g[4];
#pragma unroll
        for (int G = 0; G < 4; G++) g[G] = upk_sum(acc[G]);

        // ---- reduce over the 16 k-slices (stays within half-warp) ----
#pragma unroll
        for (int m = 1; m < 16; m <<= 1) {
#pragma unroll
            for (int G = 0; G < 4; G++)
                g[G] += __shfl_xor_sync(0xffffffffu, g[G], m);
        }

        if (isCell) {
            float gi = g[0] + bias[0] + g0next[0];
            float gf = g[1] + bias[1] + g0next[1];
            float gc = g[2] + bias[2] + g0next[2];
            float go = g[3] + bias[3] + g0next[3];
            // NOTE: for l>0 g0next stays 0; for l==0 it holds G0[t] right now.
            cst = sigf(gf) * cst + sigf(gi) * tanhf(gc);
            float h = sigf(go) * tanhf(cst);

            // push h to all 4 CTAs' sh_h[t&1][J]
            uint32_t laddr = h_base + (uint32_t)(((t & 1) * 128 + J) * 4);
#pragma unroll
            for (uint32_t r = 0; r < 4; r++)
                st_cluster_f32(mapa_r(laddr, r), h);

            if (l < 2) stg_rel_f32(&Xout[t * 128 + J], h);
            else if (t >= TT - 64) d_LastH[(t - (TT - 64)) * 128 + J] = h;

            if (l == 0 && t + 1 < TT) {
#pragma unroll
                for (int G = 0; G < 4; G++)
                    g0next[G] = __ldg(&G0[(t + 1) * 512 + G * 128 + J]);
            }

            // signal: one arrival per cell thread on every CTA's barrier (4x32x4=128 each)
#pragma unroll
            for (uint32_t r = 0; r < 4; r++)
                mbar_arrive_cluster(mapa_r(mbar_a, r));
        }

        mbar_wait_parity(mbar_a, (uint32_t)(t & 1));

        if (l < 2 && c == 0 && tid == 0) st_rel(&g_XFlag[l], t + 1);
    }
    cluster_sync_();
}

// ---------------- final FC head: 64 blocks x 128 threads ----------------
__global__ void fc_kernel(const float* __restrict__ W1, const float* __restrict__ b1,
                          const float* __restrict__ W2, const float* __restrict__ b2,
                          float* __restrict__ out)
{
    int b = blockIdx.x, tid = threadIdx.x;
    __shared__ float sh[128];
    __shared__ float red[128];
    sh[tid] = d_LastH[b * 128 + tid];
    __syncthreads();
    float s = b1[tid];
    const float* w = W1 + tid * 128;
#pragma unroll 4
    for (int k = 0; k < 128; k++) s += w[k] * sh[k];
    s = fmaxf(s, 0.f) * W2[tid];
    red[tid] = s; __syncthreads();
    for (int off = 64; off; off >>= 1) { if (tid < off) red[tid] += red[tid + off]; __syncthreads(); }
    if (tid == 0) out[b] = 1.f / (1.f + expf(-(red[0] + b2[0])));
}

// ---------------- host ----------------
static void launch_gemm(const float* A, const float* B, float* C, const float* bias,
                        int M, int N, int K, int lda, int ldb, int ldc,
                        long long sA, int divA, long long sB, int divB, long long sC,
                        int batch, float alpha, int transB, int accum)
{
    dim3 grid((N + 63) / 64, (M + 63) / 64, batch), blk(16, 16);
    gemm_k<<<grid, blk>>>(A, B, C, bias, M, N, K, lda, ldb, ldc,
                          sA, divA, sB, divB, sC, alpha, transB, accum);
}

template <typename T>
static float* sym_addr(const T& s)
{
    void* p = nullptr;
    cudaGetSymbolAddress(&p, s);
    return (float*)p;
}

extern "C" void kernel_launch(void* const* d_in, const int* in_sizes, int n_in,
                              void* d_out, int out_size)
{
    const float* sp_emo = (const float*)d_in[0];   // (16,512,25)
    const float* li_emo = (const float*)d_in[1];   // (64,512,25)
    const float* sp_3d  = (const float*)d_in[2];   // (16,512,58)
    const float* li_3d  = (const float*)d_in[3];   // (64,512,58)
    const float* pf     = (const float*)d_in[4];   // (16,128)

    // 'repeat_interleave' scalar sits at dict index 5; weights start after it.
    int off = (in_sizes[5] == 1) ? 1 : 0;
    const float* W_em = (const float*)d_in[5 + off],  *b_em = (const float*)d_in[6 + off];
    const float* W_3d = (const float*)d_in[7 + off],  *b_3d = (const float*)d_in[8 + off];
    const float* Wq_e = (const float*)d_in[9 + off],  *bq_e = (const float*)d_in[10 + off];
    const float* Wk_e = (const float*)d_in[11 + off], *bk_e = (const float*)d_in[12 + off];
    const float* Wv_e = (const float*)d_in[13 + off], *bv_e = (const float*)d_in[14 + off];
    const float* Wq_d = (const float*)d_in[15 + off], *bq_d = (const float*)d_in[16 + off];
    const float* Wk_d = (const float*)d_in[17 + off], *bk_d = (const float*)d_in[18 + off];
    const float* Wv_d = (const float*)d_in[19 + off], *bv_d = (const float*)d_in[20 + off];
    const float* W_fus = (const float*)d_in[21 + off], *b_fus = (const float*)d_in[22 + off];
    const float* W_fc1 = (const float*)d_in[23 + off], *b_fc1 = (const float*)d_in[24 + off];
    const float* W_fc2 = (const float*)d_in[25 + off], *b_fc2 = (const float*)d_in[26 + off];
    const float* W_ih = (const float*)d_in[27 + off];    // (3,512,128)
    const float* W_hh = (const float*)d_in[28 + off];    // (3,512,128)
    const float* b_ih = (const float*)d_in[29 + off];    // (3,512)
    const float* b_hh = (const float*)d_in[30 + off];    // (3,512)

    float* pLE    = sym_addr(d_LE);
    float* pLD    = sym_addr(d_LD);
    float* pQe    = sym_addr(d_Qe);
    float* pQd    = sym_addr(d_Qd);
    float* pSRCe  = sym_addr(d_SRCe);
    float* pSRCd  = sym_addr(d_SRCd);
    float* pKe    = sym_addr(d_Ke);
    float* pVe    = sym_addr(d_Ve);
    float* pKd    = sym_addr(d_Kd);
    float* pVd    = sym_addr(d_Vd);
    float* pS     = sym_addr(d_S);
    float* pFeatE = sym_addr(d_FeatE);
    float* pFeatD = sym_addr(d_FeatD);
    float* pFlat  = sym_addr(d_Flat);

    const float inv_sqrt_d = 1.0f / sqrtf(128.0f);

    reset_flags<<<1, 32>>>();
    fill_pf<<<16, 128>>>(pf);

    // --- encoders ---
    launch_gemm(li_emo, W_em, pLE, b_em, 512, 128, 25, 25, 25, 128,
                512LL * 25, 1, 0, 1, 512LL * 128, 64, 1.f, 1, 0);
    launch_gemm(sp_emo, W_em, pSRCe + 128, b_em, 512, 128, 25, 25, 25, 128,
                512LL * 25, 1, 0, 1, 513LL * 128, 16, 1.f, 1, 0);
    launch_gemm(li_3d, W_3d, pLD, b_3d, 512, 128, 58, 58, 58, 128,
                512LL * 58, 1, 0, 1, 512LL * 128, 64, 1.f, 1, 0);
    launch_gemm(sp_3d, W_3d, pSRCd + 128, b_3d, 512, 128, 58, 58, 58, 128,
                512LL * 58, 1, 0, 1, 513LL * 128, 16, 1.f, 1, 0);

    // --- QKV ---
    launch_gemm(pSRCe, Wk_e, pKe, bk_e, 513, 128, 128, 128, 128, 128,
                513LL * 128, 1, 0, 1, 513LL * 128, 16, 1.f, 1, 0);
    launch_gemm(pSRCe, Wv_e, pVe, bv_e, 513, 128, 128, 128, 128, 128,
                513LL * 128, 1, 0, 1, 513LL * 128, 16, 1.f, 1, 0);
    launch_gemm(pLE, Wq_e, pQe, bq_e, 512, 128, 128, 128, 128, 128,
                512LL * 128, 1, 0, 1, 512LL * 128, 64, 1.f, 1, 0);
    launch_gemm(pSRCd, Wk_d, pKd, bk_d, 513, 128, 128, 128, 128, 128,
                513LL * 128, 1, 0, 1, 513LL * 128, 16, 1.f, 1, 0);
    launch_gemm(pSRCd, Wv_d, pVd, bv_d, 513, 128, 128, 128, 128, 128,
                513LL * 128, 1, 0, 1, 513LL * 128, 16, 1.f, 1, 0);
    launch_gemm(pLD, Wq_d, pQd, bq_d, 512, 128, 128, 128, 128, 128,
                512LL * 128, 1, 0, 1, 512LL * 128, 64, 1.f, 1, 0);

    // --- attention (emo) ---
    launch_gemm(pQe, pKe, pS, nullptr, 512, 513, 128, 128, 128, 513,
                512LL * 128, 1, 513LL * 128, 4, 512LL * 513, 64, inv_sqrt_d, 1, 0);
    softmax_rows<<<64 * 512, 128>>>(pS, 513);
    launch_gemm(pS, pVe, pFeatE, nullptr, 512, 128, 513, 513, 128, 128,
                512LL * 513, 1, 513LL * 128, 4, 512LL * 128, 64, 1.f, 0, 0);

    // --- attention (3dmm) ---
    launch_gemm(pQd, pKd, pS, nullptr, 512, 513, 128, 128, 128, 513,
                512LL * 128, 1, 513LL * 128, 4, 512LL * 513, 64, inv_sqrt_d, 1, 0);
    softmax_rows<<<64 * 512, 128>>>(pS, 513);
    launch_gemm(pS, pVd, pFeatD, nullptr, 512, 128, 513, 513, 128, 128,
                512LL * 513, 1, 513LL * 128, 4, 512LL * 128, 64, 1.f, 0, 0);

    // --- fusion, written directly into flat (t*64+b, d) layout ---
    launch_gemm(pFeatE, W_fus, pFlat, b_fus, 512, 128, 128, 128, 256, 64 * 128,
                512LL * 128, 1, 0, 1, 128LL, 64, 1.f, 1, 0);
    launch_gemm(pFeatD, W_fus + 128, pFlat, nullptr, 512, 128, 128, 128, 256, 64 * 128,
                512LL * 128, 1, 0, 1, 128LL, 64, 1.f, 1, 1);

    // --- G0 = flat @ W_ih[0]^T + b_ih[0]   (reuses d_S storage) ---
    launch_gemm(pFlat, W_ih, pS, b_ih, TT, 512, 128, 128, 128, 512,
                0, 1, 0, 1, 0, 1, 1.f, 1, 0);

    // --- sequential 3-layer LSTM: 3 clusters x 4 CTAs ---
    lstm_kernel<<<12, 512>>>(pS, W_ih, W_hh, b_ih, b_hh);

    // --- head ---
    fc_kernel<<<64, 128>>>(W_fc1, b_fc1, W_fc2, b_fc2, (float*)d_out);
}